// round 15
// baseline (speedup 1.0000x reference)
#include <cuda_runtime.h>
#include <cuda_bf16.h>
#include <cstdint>

#define NN 100000
#define NE 640000
#define DD 128

#if defined(__CUDA_ARCH_FEAT_SM103_ALL) || defined(__CUDA_ARCH_FEAT_SM100_ALL) || \
    defined(__CUDA_ARCH_SPECIFIC__) || defined(__CUDA_ARCH_FEAT_SM101_ALL)
#define HAS_TCGEN05 1
#else
#define HAS_TCGEN05 0
#endif

// ----------------------------- device scratch -------------------------------
__device__ int   g_deg[NN];
__device__ int   g_rowstart[NN + 1];
__device__ int   g_cursor[NN];
__device__ int   g_bsum[256];
__device__ int   g_csr[NE];
__device__ float g_mean[(size_t)NN * DD];
__device__ float g_h[(size_t)NN * DD];
// Pre-converted W images: [layer][WrH|WrL|WlH|WlL], each seg 32KB, SW128 blocked
__device__ unsigned char g_wpre[2][4 * 32768];

// ----------------------------- PTX helpers ----------------------------------
static __device__ __forceinline__ uint32_t smem_u32(const void* p) {
    uint32_t a;
    asm("{ .reg .u64 t; cvta.to.shared.u64 t, %1; cvt.u32.u64 %0, t; }"
        : "=r"(a) : "l"(p));
    return a;
}

#if HAS_TCGEN05
static __device__ __forceinline__ uint32_t elect_one_pred() {
    uint32_t pred;
    asm volatile(
        "{\n\t.reg .pred p;\n\t"
        "elect.sync _|p, 0xFFFFFFFF;\n\t"
        "selp.b32 %0, 1, 0, p;\n\t}"
        : "=r"(pred));
    return pred;
}

#define TCGEN05_ALLOC(smem_addr, nCols) \
    asm volatile("tcgen05.alloc.cta_group::1.sync.aligned.shared::cta.b32 [%0], %1;" \
                 :: "r"((uint32_t)(smem_addr)), "r"((uint32_t)(nCols)) : "memory")
#define TCGEN05_RELQ() \
    asm volatile("tcgen05.relinquish_alloc_permit.cta_group::1.sync.aligned;")
#define TCGEN05_DEALLOC(tmem_addr, nCols) \
    asm volatile("tcgen05.dealloc.cta_group::1.sync.aligned.b32 %0, %1;" \
                 :: "r"(tmem_addr), "r"((uint32_t)(nCols)))
#define TCGEN05_COMMIT(mbar) \
    asm volatile("tcgen05.commit.cta_group::1.mbarrier::arrive::one.shared::cluster.b64 [%0];" \
                 :: "r"((uint32_t)(mbar)) : "memory")
#define TCGEN05_WAIT_LD()  asm volatile("tcgen05.wait::ld.sync.aligned;" ::: "memory")
#define TCGEN05_WAIT_ST()  asm volatile("tcgen05.wait::st.sync.aligned;" ::: "memory")
#define TCGEN05_FENCE_AFTER()  asm volatile("tcgen05.fence::after_thread_sync;" ::: "memory")
#define TCGEN05_FENCE_BEFORE() asm volatile("tcgen05.fence::before_thread_sync;" ::: "memory")
#define FENCE_PA() asm volatile("fence.proxy.async.shared::cta;" ::: "memory")

#define MBARRIER_INIT(m, c) \
    asm volatile("mbarrier.init.shared.b64 [%0], %1;" :: "r"((uint32_t)(m)), "r"((uint32_t)(c)) : "memory")
#define MBARRIER_INVAL(m) \
    asm volatile("mbarrier.inval.shared.b64 [%0];" :: "r"((uint32_t)(m)) : "memory")

#define MBARRIER_WAIT_PARITY(mbar_smem_addr, phase_parity) do { \
    uint32_t _mbar = (uint32_t)(mbar_smem_addr); \
    uint32_t _parity = (uint32_t)(phase_parity); \
    uint32_t _done; \
    asm volatile( \
        "{\n\t.reg .pred p;\n\t" \
        "mbarrier.try_wait.parity.acquire.cta.shared::cta.b64 p, [%1], %2;\n\t" \
        "selp.b32 %0, 1, 0, p;\n\t}" \
        : "=r"(_done) : "r"(_mbar), "r"(_parity) : "memory"); \
    if (!_done) { \
        asm volatile( \
            "{\n\t.reg .pred P1;\n\t" \
            "WAIT_LOOP_%=:\n\t" \
            "mbarrier.try_wait.parity.acquire.cta.shared::cta.b64 P1, [%0], %1, 0x989680;\n\t" \
            "@P1 bra.uni WAIT_DONE_%=;\n\t" \
            "bra.uni WAIT_LOOP_%=;\n\t" \
            "WAIT_DONE_%=:\n\t}" \
            :: "r"(_mbar), "r"(_parity) : "memory"); \
    } \
} while (0)

#define TCGEN05_LD_32X32B_X32(r, tmem_addr) \
    asm volatile( \
        "tcgen05.ld.sync.aligned.32x32b.x32.b32 " \
        "{%0, %1, %2, %3, %4, %5, %6, %7, " \
        " %8, %9, %10, %11, %12, %13, %14, %15, " \
        " %16, %17, %18, %19, %20, %21, %22, %23, " \
        " %24, %25, %26, %27, %28, %29, %30, %31}, [%32];" \
        : "=r"((r)[0]),  "=r"((r)[1]),  "=r"((r)[2]),  "=r"((r)[3]), \
          "=r"((r)[4]),  "=r"((r)[5]),  "=r"((r)[6]),  "=r"((r)[7]), \
          "=r"((r)[8]),  "=r"((r)[9]),  "=r"((r)[10]), "=r"((r)[11]), \
          "=r"((r)[12]), "=r"((r)[13]), "=r"((r)[14]), "=r"((r)[15]), \
          "=r"((r)[16]), "=r"((r)[17]), "=r"((r)[18]), "=r"((r)[19]), \
          "=r"((r)[20]), "=r"((r)[21]), "=r"((r)[22]), "=r"((r)[23]), \
          "=r"((r)[24]), "=r"((r)[25]), "=r"((r)[26]), "=r"((r)[27]), \
          "=r"((r)[28]), "=r"((r)[29]), "=r"((r)[30]), "=r"((r)[31]) \
        : "r"(tmem_addr))

#define TCGEN05_ST_32X32B_X32(tmem_addr, r) \
    asm volatile( \
        "tcgen05.st.sync.aligned.32x32b.x32.b32 [%0], " \
        "{%1, %2, %3, %4, %5, %6, %7, %8, " \
        " %9, %10, %11, %12, %13, %14, %15, %16, " \
        " %17, %18, %19, %20, %21, %22, %23, %24, " \
        " %25, %26, %27, %28, %29, %30, %31, %32};" \
        :: "r"(tmem_addr), \
           "r"((r)[0]),  "r"((r)[1]),  "r"((r)[2]),  "r"((r)[3]), \
           "r"((r)[4]),  "r"((r)[5]),  "r"((r)[6]),  "r"((r)[7]), \
           "r"((r)[8]),  "r"((r)[9]),  "r"((r)[10]), "r"((r)[11]), \
           "r"((r)[12]), "r"((r)[13]), "r"((r)[14]), "r"((r)[15]), \
           "r"((r)[16]), "r"((r)[17]), "r"((r)[18]), "r"((r)[19]), \
           "r"((r)[20]), "r"((r)[21]), "r"((r)[22]), "r"((r)[23]), \
           "r"((r)[24]), "r"((r)[25]), "r"((r)[26]), "r"((r)[27]), \
           "r"((r)[28]), "r"((r)[29]), "r"((r)[30]), "r"((r)[31]) \
        : "memory")

// TS-mode f16 MMA (A in TMEM, B via SMEM descriptor) — verbatim ptx_helpers.
#define TCGEN05_MMA_F16(d_tmem, a_tmem, b_smem_desc, idesc, enable_d) do { \
    uint32_t _enable = (enable_d) ? 1 : 0; \
    uint32_t _zero = 0; \
    asm volatile( \
        "{\n\t" \
        ".reg .pred p;\n\t" \
        "setp.ne.u32 p, %6, 0;\n\t" \
        "tcgen05.mma.cta_group::1.kind::f16 [%0], [%1], %2, %3, " \
        "{%4, %4, %4, %4}, p;\n\t" \
        "}" \
        :: "r"(d_tmem), "r"(a_tmem), "l"(b_smem_desc), "r"(idesc), \
           "r"(_zero), "r"(_zero), "r"(_enable) \
        : "memory"); \
} while(0)

static constexpr uint64_t SMEM_DESC_BASE_SW128 =
    (uint64_t(2) << 61) | (uint64_t(1) << 46) | (uint64_t(64) << 32) | (uint64_t(1) << 16);
#define MAKE_SMEM_DESC(base_addr) \
    (SMEM_DESC_BASE_SW128 | ((uint64_t)((base_addr) >> 4) & 0x3FFF))
#endif  // HAS_TCGEN05

// ------------------------------ CSR build -----------------------------------
__global__ void k_zero() {
    int i = blockIdx.x * 256 + threadIdx.x;
    if (i < NN) g_deg[i] = 0;
}

__global__ void k_hist(const int* __restrict__ ei) {
    int e = blockIdx.x * 256 + threadIdx.x;
    if (e < NE) {
        int d = ei[NE + e];
        atomicAdd(&g_deg[d], 1);
    }
}

__global__ void k_scanA() {
    __shared__ int sh[256];
    int b = blockIdx.x, t = threadIdx.x;
    int base = b * 512 + t * 2;
    int d0 = (base     < NN) ? g_deg[base]     : 0;
    int d1 = (base + 1 < NN) ? g_deg[base + 1] : 0;
    int s = d0 + d1;
    sh[t] = s; __syncthreads();
    for (int off = 1; off < 256; off <<= 1) {
        int v = (t >= off) ? sh[t - off] : 0;
        __syncthreads();
        sh[t] += v;
        __syncthreads();
    }
    int excl = sh[t] - s;
    if (base     < NN) g_rowstart[base]     = excl;
    if (base + 1 < NN) g_rowstart[base + 1] = excl + d0;
    if (t == 255) g_bsum[b] = sh[255];
}

__global__ void k_scanB() {
    __shared__ int sh[256];
    int t = threadIdx.x;
    int v = (t < 196) ? g_bsum[t] : 0;
    sh[t] = v; __syncthreads();
    for (int off = 1; off < 256; off <<= 1) {
        int u = (t >= off) ? sh[t - off] : 0;
        __syncthreads();
        sh[t] += u;
        __syncthreads();
    }
    if (t < 196) g_bsum[t] = sh[t] - v;   // exclusive
    if (t == 255) g_rowstart[NN] = sh[255];
}

__global__ void k_scanC() {
    int b = blockIdx.x, t = threadIdx.x;
    int off = g_bsum[b];
    int base = b * 512 + t * 2;
#pragma unroll
    for (int j = 0; j < 2; j++) {
        int i = base + j;
        if (i < NN) {
            int v = g_rowstart[i] + off;
            g_rowstart[i] = v;
            g_cursor[i]   = v;
        }
    }
}

__global__ void k_scatter(const int* __restrict__ ei) {
    int e = blockIdx.x * 256 + threadIdx.x;
    if (e < NE) {
        int s = ei[e];
        int d = ei[NE + e];
        int p = atomicAdd(&g_cursor[d], 1);
        g_csr[p] = s;
    }
}

// ------------------------------ aggregation ---------------------------------
__global__ void k_agg(const float* __restrict__ feat, float* __restrict__ om) {
    int w = (blockIdx.x * blockDim.x + threadIdx.x) >> 5;
    int lane = threadIdx.x & 31;
    if (w >= NN) return;
    int beg = g_rowstart[w], end = g_rowstart[w + 1];
    float4 a = make_float4(0.f, 0.f, 0.f, 0.f);
    int i = beg;
#pragma unroll 1
    for (; i + 2 <= end; i += 2) {
        int s0 = g_csr[i];
        int s1 = g_csr[i + 1];
        float4 v0 = ((const float4*)(feat + (size_t)s0 * DD))[lane];
        float4 v1 = ((const float4*)(feat + (size_t)s1 * DD))[lane];
        a.x += v0.x + v1.x; a.y += v0.y + v1.y;
        a.z += v0.z + v1.z; a.w += v0.w + v1.w;
    }
    if (i < end) {
        int s = g_csr[i];
        float4 v = ((const float4*)(feat + (size_t)s * DD))[lane];
        a.x += v.x; a.y += v.y; a.z += v.z; a.w += v.w;
    }
    float inv = 1.0f / (float)max(end - beg, 1);
    a.x *= inv; a.y *= inv; a.z *= inv; a.w *= inv;
    ((float4*)(om + (size_t)w * DD))[lane] = a;
}

// --------------------------- W pre-conversion --------------------------------
static __device__ __forceinline__ void split_pack(float a, float b,
                                                  uint32_t& hi, uint32_t& lo) {
    __nv_bfloat16 ah = __float2bfloat16(a);
    __nv_bfloat16 bh = __float2bfloat16(b);
    __nv_bfloat16 al = __float2bfloat16(a - __bfloat162float(ah));
    __nv_bfloat16 bl = __float2bfloat16(b - __bfloat162float(bh));
    __nv_bfloat162 H = __halves2bfloat162(ah, bh);
    __nv_bfloat162 L = __halves2bfloat162(al, bl);
    hi = *reinterpret_cast<uint32_t*>(&H);
    lo = *reinterpret_cast<uint32_t*>(&L);
}

static __device__ __forceinline__ void wconv(const float* __restrict__ src,
                                             unsigned char* __restrict__ hi_seg,
                                             unsigned char* __restrict__ lo_seg,
                                             int tid) {
#pragma unroll 4
    for (int i = 0; i < 16; i++) {
        int idx = tid + 256 * i;
        int r   = idx >> 5;
        int c4  = idx & 31;
        float4 v = *(const float4*)(src + (size_t)r * DD + c4 * 4);
        uint32_t h01, l01, h23, l23;
        split_pack(v.x, v.y, h01, l01);
        split_pack(v.z, v.w, h23, l23);
        uint32_t off = ((uint32_t)(c4 >> 4) * 16u + (uint32_t)(r >> 3)) * 1024u
                     + (uint32_t)(r & 7) * 128u + (uint32_t)(c4 & 15) * 8u;
        uint32_t sw = off ^ ((off >> 3) & 0x70);
        *(uint64_t*)(hi_seg + sw) = ((uint64_t)h01) | ((uint64_t)h23 << 32);
        *(uint64_t*)(lo_seg + sw) = ((uint64_t)l01) | ((uint64_t)l23 << 32);
    }
}

__global__ void k_wprep(const float* __restrict__ W1l, const float* __restrict__ W1r,
                        const float* __restrict__ W2l, const float* __restrict__ W2r) {
    int l = blockIdx.x;
    const float* Wr = l ? W2r : W1r;
    const float* Wl = l ? W2l : W1l;
    unsigned char* base = g_wpre[l];
    wconv(Wr, base,             base + 32768,     threadIdx.x);
    wconv(Wl, base + 2 * 32768, base + 3 * 32768, threadIdx.x);
}

// ------------------------------- GEMM (tcgen05 TS) ---------------------------
// 4 row-tiles (512 nodes) per CTA. TMEM 512 cols: D ping-pong 0-127/128-255,
// A staging 256-511 (xH|xL|mH|mL, reused per tile). One commit per mbarrier.
#define SM_BIAS   64
#define SM_W      1024                       // 4 x 32KB: WrH|WrL|WlH|WlL
#define SM_TOTAL  (SM_W + 4 * 32768 + 128)   // ~132.2 KB

#define TMEM_COLS 512
#define TM_AXH 256
#define TM_AXL 320
#define TM_AMH 384
#define TM_AML 448

#define MMA_IDESC 0x8200490u

#if HAS_TCGEN05
// Stage a 128x128 fp32 tile -> TMEM bf16x2 hi/lo at given columns.
static __device__ __forceinline__ void stage_A(const float* __restrict__ src,
                                               int row0, int n, uint32_t tmem,
                                               int col_hi, int col_lo, int tid) {
    int row  = tid & 127;
    int half = tid >> 7;
    int gr   = row0 + row;
    uint32_t hi[32], lo[32];
    if (gr < n) {
        const float4* sr = (const float4*)(src + (size_t)gr * DD) + half * 16;
#pragma unroll
        for (int q = 0; q < 16; q++) {
            float4 v = sr[q];
            split_pack(v.x, v.y, hi[2 * q],     lo[2 * q]);
            split_pack(v.z, v.w, hi[2 * q + 1], lo[2 * q + 1]);
        }
    } else {
#pragma unroll
        for (int q = 0; q < 32; q++) { hi[q] = 0u; lo[q] = 0u; }
    }
    uint32_t base = tmem + (((uint32_t)(row >> 5)) << 21) + half * 32;
    TCGEN05_ST_32X32B_X32(base + col_hi, hi);
    TCGEN05_ST_32X32B_X32(base + col_lo, lo);
}

// 6 combos x 8 k-steps into D at d_off (fresh accumulate: first MMA acc=0).
static __device__ __forceinline__ void mma_batch(uint32_t tmem, uint32_t d_off,
                                                 uint32_t sb) {
    uint64_t dRh = MAKE_SMEM_DESC(sb + SM_W);
    uint64_t dRl = MAKE_SMEM_DESC(sb + SM_W + 32768);
    uint64_t dLh = MAKE_SMEM_DESC(sb + SM_W + 2 * 32768);
    uint64_t dLl = MAKE_SMEM_DESC(sb + SM_W + 3 * 32768);
    uint32_t ac[6] = {TM_AXH, TM_AXH, TM_AXL, TM_AMH, TM_AMH, TM_AML};
    uint64_t wd[6] = {dRh, dRl, dRh, dLh, dLl, dLh};
    bool acc = false;
#pragma unroll 1
    for (int c = 0; c < 6; c++) {
#pragma unroll
        for (int k = 0; k < 8; k++) {
            uint64_t off = (uint64_t)((k >> 2) * 1024 + (k & 3) * 2);
            TCGEN05_MMA_F16(tmem + d_off, tmem + ac[c] + k * 8, wd[c] + off,
                            MMA_IDESC, acc);
            acc = true;
        }
    }
}

// Epilogue for one tile: warp w reads rows (w%4)*32+lane, cols (w/4)*64..+63.
static __device__ __forceinline__ void epilogue(uint32_t tmem, uint32_t d_off,
                                                const float* bs, float* outp,
                                                int row0, int n, int relu,
                                                int wid, int lid) {
    int r = row0 + (wid & 3) * 32 + lid;
    int cbase = (wid >> 2) * 64;
#pragma unroll
    for (int cc = 0; cc < 2; cc++) {
        int cb = cbase + cc * 32;
        uint32_t regs[32];
        TCGEN05_LD_32X32B_X32(regs, tmem + d_off + cb);
        TCGEN05_WAIT_LD();
        if (r < n) {
            float4* orow = (float4*)(outp + (size_t)r * DD + cb);
#pragma unroll
            for (int q = 0; q < 8; q++) {
                float4 o;
                o.x = __uint_as_float(regs[4 * q + 0]) + bs[cb + 4 * q + 0];
                o.y = __uint_as_float(regs[4 * q + 1]) + bs[cb + 4 * q + 1];
                o.z = __uint_as_float(regs[4 * q + 2]) + bs[cb + 4 * q + 2];
                o.w = __uint_as_float(regs[4 * q + 3]) + bs[cb + 4 * q + 3];
                if (relu) {
                    o.x = fmaxf(o.x, 0.f); o.y = fmaxf(o.y, 0.f);
                    o.z = fmaxf(o.z, 0.f); o.w = fmaxf(o.w, 0.f);
                }
                orow[q] = o;
            }
        }
    }
}

// Stage tile + issue MMA into D buffer + commit mbar (warp0-elected).
static __device__ __forceinline__ void tile_mma(const float* feat, const float* meanf,
                                                int row0, int n, uint32_t tmem,
                                                uint32_t d_off, uint32_t sb,
                                                uint32_t mbar, int tid, int wid) {
    stage_A(feat,  row0, n, tmem, TM_AXH, TM_AXL, tid);
    stage_A(meanf, row0, n, tmem, TM_AMH, TM_AML, tid);
    TCGEN05_WAIT_ST();
    FENCE_PA();
    TCGEN05_FENCE_BEFORE();
    __syncthreads();
    if (wid == 0) {
        TCGEN05_FENCE_AFTER();
        if (elect_one_pred()) {
            mma_batch(tmem, d_off, sb);
            TCGEN05_COMMIT(mbar);
        }
    }
}
#endif

extern "C" __global__ void __launch_bounds__(256, 1)
k_gemm(const float* __restrict__ feat, const float* __restrict__ meanf,
       const uint4* __restrict__ wpre,
       const float* __restrict__ Wl, const float* __restrict__ Wr,
       const float* __restrict__ bias, float* __restrict__ outp, int n, int relu) {
    extern __shared__ char smem[];
    uint32_t sb = smem_u32(smem);
    int tid = threadIdx.x, wid = tid >> 5, lid = tid & 31;
    int row0 = blockIdx.x * 512;          // 4 tiles: row0 + t*128

#if HAS_TCGEN05
    if (wid == 0) { TCGEN05_ALLOC(sb, TMEM_COLS); } else { TCGEN05_RELQ(); }
    if (tid == 0) {
        MBARRIER_INIT(sb + 8,  1); MBARRIER_INIT(sb + 16, 1);
        MBARRIER_INIT(sb + 24, 1); MBARRIER_INIT(sb + 32, 1);
    }
    if (tid < 128) ((float*)(smem + SM_BIAS))[tid] = bias[tid];
    __syncthreads();
    uint32_t tmem;
    asm volatile("ld.shared.b32 %0, [%1];" : "=r"(tmem) : "r"(sb));

    // W image raw copy (128KB) — once per CTA, serves all 4 tiles
    {
        uint4* dst = (uint4*)(smem + SM_W);
#pragma unroll 8
        for (int i = tid; i < 8192; i += 256) dst[i] = wpre[i];
    }
    const float* bs = (const float*)(smem + SM_BIAS);

    // tile 0 -> D0, b0
    tile_mma(feat, meanf, row0, n, tmem, 0, sb, sb + 8, tid, wid);
    MBARRIER_WAIT_PARITY(sb + 8, 0);      // A cols free, D0 valid
    TCGEN05_FENCE_AFTER();

    // tile 1 -> D1, b1; then epilogue D0 overlaps MMA1
    tile_mma(feat, meanf, row0 + 128, n, tmem, 128, sb, sb + 16, tid, wid);
    epilogue(tmem, 0, bs, outp, row0, n, relu, wid, lid);
    MBARRIER_WAIT_PARITY(sb + 16, 0);
    TCGEN05_FENCE_AFTER();
    __syncthreads();                      // all epilogue-D0 reads done

    // tile 2 -> D0, b2; epilogue D1 overlaps MMA2
    tile_mma(feat, meanf, row0 + 256, n, tmem, 0, sb, sb + 24, tid, wid);
    epilogue(tmem, 128, bs, outp, row0 + 128, n, relu, wid, lid);
    MBARRIER_WAIT_PARITY(sb + 24, 0);
    TCGEN05_FENCE_AFTER();
    __syncthreads();                      // all epilogue-D1 reads done

    // tile 3 -> D1, b3; epilogue D0 (tile2) overlaps MMA3
    tile_mma(feat, meanf, row0 + 384, n, tmem, 128, sb, sb + 32, tid, wid);
    epilogue(tmem, 0, bs, outp, row0 + 256, n, relu, wid, lid);
    MBARRIER_WAIT_PARITY(sb + 32, 0);
    TCGEN05_FENCE_AFTER();
    epilogue(tmem, 128, bs, outp, row0 + 384, n, relu, wid, lid);

    TCGEN05_FENCE_BEFORE();
    __syncthreads();
    if (tid == 0) {
        MBARRIER_INVAL(sb + 8);  MBARRIER_INVAL(sb + 16);
        MBARRIER_INVAL(sb + 24); MBARRIER_INVAL(sb + 32);
    }
    __syncthreads();
    if (wid == 0) TCGEN05_DEALLOC(tmem, TMEM_COLS);
#else
    // Scalar fallback for the non-arch-specific compile pass (never runs on GB300).
    float* Wl_s = (float*)(smem);
    float* Wr_s = (float*)(smem + 65536);
    for (int i = tid; i < 128 * 128; i += 256) {
        Wl_s[i] = Wl[i];
        Wr_s[i] = Wr[i];
    }
    __syncthreads();
    for (int t = 0; t < 4; t++) {
        if (tid < 128) {
            int r = row0 + t * 128 + tid;
            if (r < n) {
                for (int c = 0; c < DD; c++) {
                    float acc = bias[c];
                    const float* wl = Wl_s + c * DD;
                    const float* wr = Wr_s + c * DD;
                    const float* xr = feat  + (size_t)r * DD;
                    const float* mr = meanf + (size_t)r * DD;
                    for (int k = 0; k < DD; k++)
                        acc += xr[k] * wr[k] + mr[k] * wl[k];
                    if (relu) acc = fmaxf(acc, 0.f);
                    outp[(size_t)r * DD + c] = acc;
                }
            }
        }
    }
#endif
}

// ------------------------------- launcher -----------------------------------
extern "C" void kernel_launch(void* const* d_in, const int* in_sizes, int n_in,
                              void* d_out, int out_size) {
    const float* x   = (const float*)d_in[0];
    const int*   ei  = (const int*)d_in[1];     // int32! (JAX x64 disabled)
    const float* W1l = (const float*)d_in[2];
    const float* W1r = (const float*)d_in[3];
    const float* b1  = (const float*)d_in[4];
    const float* W2l = (const float*)d_in[5];
    const float* W2r = (const float*)d_in[6];
    const float* b2  = (const float*)d_in[7];
    float*       out = (float*)d_out;

    cudaFuncSetAttribute(k_gemm, cudaFuncAttributeMaxDynamicSharedMemorySize, SM_TOTAL);

    void* pmean = nullptr;
    void* ph = nullptr;
    void* pw = nullptr;
    cudaGetSymbolAddress(&pmean, g_mean);
    cudaGetSymbolAddress(&ph, g_h);
    cudaGetSymbolAddress(&pw, g_wpre);
    float* mean = (float*)pmean;
    float* h    = (float*)ph;
    const uint4* w0 = (const uint4*)pw;
    const uint4* w1 = (const uint4*)((const unsigned char*)pw + 4 * 32768);

    // CSR build (shared by both layers) + W pre-conversion
    k_zero   <<<(NN + 255) / 256, 256>>>();
    k_hist   <<<(NE + 255) / 256, 256>>>(ei);
    k_wprep  <<<2, 256>>>(W1l, W1r, W2l, W2r);
    k_scanA  <<<196, 256>>>();
    k_scanB  <<<1,   256>>>();
    k_scanC  <<<196, 256>>>();
    k_scatter<<<(NE + 255) / 256, 256>>>(ei);

    int gemm_blocks = (NN + 511) / 512;   // 196

    // layer 1
    k_agg<<<NN / 8, 256>>>(x, mean);      // 12500 blocks, warp/node
    k_gemm<<<gemm_blocks, 256, SM_TOTAL>>>(x, mean, w0, W1l, W1r, b1, h, NN, 1);

    // layer 2
    k_agg<<<NN / 8, 256>>>(h, mean);
    k_gemm<<<gemm_blocks, 256, SM_TOTAL>>>(h, mean, w1, W2l, W2r, b2, out, NN, 0);
}

// round 16
// speedup vs baseline: 1.1561x; 1.1561x over previous
#include <cuda_runtime.h>
#include <cuda_bf16.h>
#include <cstdint>

#define NN 100000
#define NE 640000
#define DD 128

#if defined(__CUDA_ARCH_FEAT_SM103_ALL) || defined(__CUDA_ARCH_FEAT_SM100_ALL) || \
    defined(__CUDA_ARCH_SPECIFIC__) || defined(__CUDA_ARCH_FEAT_SM101_ALL)
#define HAS_TCGEN05 1
#else
#define HAS_TCGEN05 0
#endif

// ----------------------------- device scratch -------------------------------
__device__ int   g_deg[NN];
__device__ int   g_rowstart[NN + 1];
__device__ int   g_cursor[NN];
__device__ int   g_bsum[256];
__device__ int   g_csr[NE];
__device__ float g_mean[(size_t)NN * DD];
__device__ float g_h[(size_t)NN * DD];
// Pre-converted W images: [layer][WrH|WrL|WlH|WlL], each seg 32KB, SW128 blocked
__device__ unsigned char g_wpre[2][4 * 32768];

// ----------------------------- PTX helpers ----------------------------------
static __device__ __forceinline__ uint32_t smem_u32(const void* p) {
    uint32_t a;
    asm("{ .reg .u64 t; cvta.to.shared.u64 t, %1; cvt.u32.u64 %0, t; }"
        : "=r"(a) : "l"(p));
    return a;
}

#if HAS_TCGEN05
static __device__ __forceinline__ uint32_t elect_one_pred() {
    uint32_t pred;
    asm volatile(
        "{\n\t.reg .pred p;\n\t"
        "elect.sync _|p, 0xFFFFFFFF;\n\t"
        "selp.b32 %0, 1, 0, p;\n\t}"
        : "=r"(pred));
    return pred;
}

#define TCGEN05_ALLOC(smem_addr, nCols) \
    asm volatile("tcgen05.alloc.cta_group::1.sync.aligned.shared::cta.b32 [%0], %1;" \
                 :: "r"((uint32_t)(smem_addr)), "r"((uint32_t)(nCols)) : "memory")
#define TCGEN05_RELQ() \
    asm volatile("tcgen05.relinquish_alloc_permit.cta_group::1.sync.aligned;")
#define TCGEN05_DEALLOC(tmem_addr, nCols) \
    asm volatile("tcgen05.dealloc.cta_group::1.sync.aligned.b32 %0, %1;" \
                 :: "r"(tmem_addr), "r"((uint32_t)(nCols)))
#define TCGEN05_COMMIT(mbar) \
    asm volatile("tcgen05.commit.cta_group::1.mbarrier::arrive::one.shared::cluster.b64 [%0];" \
                 :: "r"((uint32_t)(mbar)) : "memory")
#define TCGEN05_WAIT_LD()  asm volatile("tcgen05.wait::ld.sync.aligned;" ::: "memory")
#define TCGEN05_WAIT_ST()  asm volatile("tcgen05.wait::st.sync.aligned;" ::: "memory")
#define TCGEN05_FENCE_AFTER()  asm volatile("tcgen05.fence::after_thread_sync;" ::: "memory")
#define TCGEN05_FENCE_BEFORE() asm volatile("tcgen05.fence::before_thread_sync;" ::: "memory")
#define FENCE_PA() asm volatile("fence.proxy.async.shared::cta;" ::: "memory")

#define MBARRIER_INIT(m, c) \
    asm volatile("mbarrier.init.shared.b64 [%0], %1;" :: "r"((uint32_t)(m)), "r"((uint32_t)(c)) : "memory")
#define MBARRIER_INVAL(m) \
    asm volatile("mbarrier.inval.shared.b64 [%0];" :: "r"((uint32_t)(m)) : "memory")

#define MBARRIER_WAIT_PARITY(mbar_smem_addr, phase_parity) do { \
    uint32_t _mbar = (uint32_t)(mbar_smem_addr); \
    uint32_t _parity = (uint32_t)(phase_parity); \
    uint32_t _done; \
    asm volatile( \
        "{\n\t.reg .pred p;\n\t" \
        "mbarrier.try_wait.parity.acquire.cta.shared::cta.b64 p, [%1], %2;\n\t" \
        "selp.b32 %0, 1, 0, p;\n\t}" \
        : "=r"(_done) : "r"(_mbar), "r"(_parity) : "memory"); \
    if (!_done) { \
        asm volatile( \
            "{\n\t.reg .pred P1;\n\t" \
            "WAIT_LOOP_%=:\n\t" \
            "mbarrier.try_wait.parity.acquire.cta.shared::cta.b64 P1, [%0], %1, 0x989680;\n\t" \
            "@P1 bra.uni WAIT_DONE_%=;\n\t" \
            "bra.uni WAIT_LOOP_%=;\n\t" \
            "WAIT_DONE_%=:\n\t}" \
            :: "r"(_mbar), "r"(_parity) : "memory"); \
    } \
} while (0)

#define TCGEN05_LD_32X32B_X32(r, tmem_addr) \
    asm volatile( \
        "tcgen05.ld.sync.aligned.32x32b.x32.b32 " \
        "{%0, %1, %2, %3, %4, %5, %6, %7, " \
        " %8, %9, %10, %11, %12, %13, %14, %15, " \
        " %16, %17, %18, %19, %20, %21, %22, %23, " \
        " %24, %25, %26, %27, %28, %29, %30, %31}, [%32];" \
        : "=r"((r)[0]),  "=r"((r)[1]),  "=r"((r)[2]),  "=r"((r)[3]), \
          "=r"((r)[4]),  "=r"((r)[5]),  "=r"((r)[6]),  "=r"((r)[7]), \
          "=r"((r)[8]),  "=r"((r)[9]),  "=r"((r)[10]), "=r"((r)[11]), \
          "=r"((r)[12]), "=r"((r)[13]), "=r"((r)[14]), "=r"((r)[15]), \
          "=r"((r)[16]), "=r"((r)[17]), "=r"((r)[18]), "=r"((r)[19]), \
          "=r"((r)[20]), "=r"((r)[21]), "=r"((r)[22]), "=r"((r)[23]), \
          "=r"((r)[24]), "=r"((r)[25]), "=r"((r)[26]), "=r"((r)[27]), \
          "=r"((r)[28]), "=r"((r)[29]), "=r"((r)[30]), "=r"((r)[31]) \
        : "r"(tmem_addr))

#define TCGEN05_ST_32X32B_X32(tmem_addr, r) \
    asm volatile( \
        "tcgen05.st.sync.aligned.32x32b.x32.b32 [%0], " \
        "{%1, %2, %3, %4, %5, %6, %7, %8, " \
        " %9, %10, %11, %12, %13, %14, %15, %16, " \
        " %17, %18, %19, %20, %21, %22, %23, %24, " \
        " %25, %26, %27, %28, %29, %30, %31, %32};" \
        :: "r"(tmem_addr), \
           "r"((r)[0]),  "r"((r)[1]),  "r"((r)[2]),  "r"((r)[3]), \
           "r"((r)[4]),  "r"((r)[5]),  "r"((r)[6]),  "r"((r)[7]), \
           "r"((r)[8]),  "r"((r)[9]),  "r"((r)[10]), "r"((r)[11]), \
           "r"((r)[12]), "r"((r)[13]), "r"((r)[14]), "r"((r)[15]), \
           "r"((r)[16]), "r"((r)[17]), "r"((r)[18]), "r"((r)[19]), \
           "r"((r)[20]), "r"((r)[21]), "r"((r)[22]), "r"((r)[23]), \
           "r"((r)[24]), "r"((r)[25]), "r"((r)[26]), "r"((r)[27]), \
           "r"((r)[28]), "r"((r)[29]), "r"((r)[30]), "r"((r)[31]) \
        : "memory")

// TS-mode f16 MMA (A in TMEM, B via SMEM descriptor) — verbatim ptx_helpers.
#define TCGEN05_MMA_F16(d_tmem, a_tmem, b_smem_desc, idesc, enable_d) do { \
    uint32_t _enable = (enable_d) ? 1 : 0; \
    uint32_t _zero = 0; \
    asm volatile( \
        "{\n\t" \
        ".reg .pred p;\n\t" \
        "setp.ne.u32 p, %6, 0;\n\t" \
        "tcgen05.mma.cta_group::1.kind::f16 [%0], [%1], %2, %3, " \
        "{%4, %4, %4, %4}, p;\n\t" \
        "}" \
        :: "r"(d_tmem), "r"(a_tmem), "l"(b_smem_desc), "r"(idesc), \
           "r"(_zero), "r"(_zero), "r"(_enable) \
        : "memory"); \
} while(0)

static constexpr uint64_t SMEM_DESC_BASE_SW128 =
    (uint64_t(2) << 61) | (uint64_t(1) << 46) | (uint64_t(64) << 32) | (uint64_t(1) << 16);
#define MAKE_SMEM_DESC(base_addr) \
    (SMEM_DESC_BASE_SW128 | ((uint64_t)((base_addr) >> 4) & 0x3FFF))
#endif  // HAS_TCGEN05

// ------------------------------ CSR build -----------------------------------
__global__ void k_zero() {
    int i = blockIdx.x * 256 + threadIdx.x;
    if (i < NN) g_deg[i] = 0;
}

__global__ void k_hist(const int* __restrict__ ei) {
    int e = blockIdx.x * 256 + threadIdx.x;
    if (e < NE) {
        int d = ei[NE + e];
        atomicAdd(&g_deg[d], 1);
    }
}

__global__ void k_scanA() {
    __shared__ int sh[256];
    int b = blockIdx.x, t = threadIdx.x;
    int base = b * 512 + t * 2;
    int d0 = (base     < NN) ? g_deg[base]     : 0;
    int d1 = (base + 1 < NN) ? g_deg[base + 1] : 0;
    int s = d0 + d1;
    sh[t] = s; __syncthreads();
    for (int off = 1; off < 256; off <<= 1) {
        int v = (t >= off) ? sh[t - off] : 0;
        __syncthreads();
        sh[t] += v;
        __syncthreads();
    }
    int excl = sh[t] - s;
    if (base     < NN) g_rowstart[base]     = excl;
    if (base + 1 < NN) g_rowstart[base + 1] = excl + d0;
    if (t == 255) g_bsum[b] = sh[255];
}

__global__ void k_scanB() {
    __shared__ int sh[256];
    int t = threadIdx.x;
    int v = (t < 196) ? g_bsum[t] : 0;
    sh[t] = v; __syncthreads();
    for (int off = 1; off < 256; off <<= 1) {
        int u = (t >= off) ? sh[t - off] : 0;
        __syncthreads();
        sh[t] += u;
        __syncthreads();
    }
    if (t < 196) g_bsum[t] = sh[t] - v;   // exclusive
    if (t == 255) g_rowstart[NN] = sh[255];
}

__global__ void k_scanC() {
    int b = blockIdx.x, t = threadIdx.x;
    int off = g_bsum[b];
    int base = b * 512 + t * 2;
#pragma unroll
    for (int j = 0; j < 2; j++) {
        int i = base + j;
        if (i < NN) {
            int v = g_rowstart[i] + off;
            g_rowstart[i] = v;
            g_cursor[i]   = v;
        }
    }
}

__global__ void k_scatter(const int* __restrict__ ei) {
    int e = blockIdx.x * 256 + threadIdx.x;
    if (e < NE) {
        int s = ei[e];
        int d = ei[NE + e];
        int p = atomicAdd(&g_cursor[d], 1);
        g_csr[p] = s;
    }
}

// ------------------------------ aggregation ---------------------------------
__global__ void k_agg(const float* __restrict__ feat, float* __restrict__ om) {
    int w = (blockIdx.x * blockDim.x + threadIdx.x) >> 5;
    int lane = threadIdx.x & 31;
    if (w >= NN) return;
    int beg = g_rowstart[w], end = g_rowstart[w + 1];
    float4 a = make_float4(0.f, 0.f, 0.f, 0.f);
    int i = beg;
#pragma unroll 1
    for (; i + 2 <= end; i += 2) {
        int s0 = g_csr[i];
        int s1 = g_csr[i + 1];
        float4 v0 = ((const float4*)(feat + (size_t)s0 * DD))[lane];
        float4 v1 = ((const float4*)(feat + (size_t)s1 * DD))[lane];
        a.x += v0.x + v1.x; a.y += v0.y + v1.y;
        a.z += v0.z + v1.z; a.w += v0.w + v1.w;
    }
    if (i < end) {
        int s = g_csr[i];
        float4 v = ((const float4*)(feat + (size_t)s * DD))[lane];
        a.x += v.x; a.y += v.y; a.z += v.z; a.w += v.w;
    }
    float inv = 1.0f / (float)max(end - beg, 1);
    a.x *= inv; a.y *= inv; a.z *= inv; a.w *= inv;
    ((float4*)(om + (size_t)w * DD))[lane] = a;
}

// --------------------------- W pre-conversion --------------------------------
static __device__ __forceinline__ void split_pack(float a, float b,
                                                  uint32_t& hi, uint32_t& lo) {
    __nv_bfloat16 ah = __float2bfloat16(a);
    __nv_bfloat16 bh = __float2bfloat16(b);
    __nv_bfloat16 al = __float2bfloat16(a - __bfloat162float(ah));
    __nv_bfloat16 bl = __float2bfloat16(b - __bfloat162float(bh));
    __nv_bfloat162 H = __halves2bfloat162(ah, bh);
    __nv_bfloat162 L = __halves2bfloat162(al, bl);
    hi = *reinterpret_cast<uint32_t*>(&H);
    lo = *reinterpret_cast<uint32_t*>(&L);
}

static __device__ __forceinline__ void wconv(const float* __restrict__ src,
                                             unsigned char* __restrict__ hi_seg,
                                             unsigned char* __restrict__ lo_seg,
                                             int tid) {
#pragma unroll 4
    for (int i = 0; i < 16; i++) {
        int idx = tid + 256 * i;
        int r   = idx >> 5;
        int c4  = idx & 31;
        float4 v = *(const float4*)(src + (size_t)r * DD + c4 * 4);
        uint32_t h01, l01, h23, l23;
        split_pack(v.x, v.y, h01, l01);
        split_pack(v.z, v.w, h23, l23);
        uint32_t off = ((uint32_t)(c4 >> 4) * 16u + (uint32_t)(r >> 3)) * 1024u
                     + (uint32_t)(r & 7) * 128u + (uint32_t)(c4 & 15) * 8u;
        uint32_t sw = off ^ ((off >> 3) & 0x70);
        *(uint64_t*)(hi_seg + sw) = ((uint64_t)h01) | ((uint64_t)h23 << 32);
        *(uint64_t*)(lo_seg + sw) = ((uint64_t)l01) | ((uint64_t)l23 << 32);
    }
}

__global__ void k_wprep(const float* __restrict__ W1l, const float* __restrict__ W1r,
                        const float* __restrict__ W2l, const float* __restrict__ W2r) {
    int l = blockIdx.x;
    const float* Wr = l ? W2r : W1r;
    const float* Wl = l ? W2l : W1l;
    unsigned char* base = g_wpre[l];
    wconv(Wr, base,             base + 32768,     threadIdx.x);
    wconv(Wl, base + 2 * 32768, base + 3 * 32768, threadIdx.x);
}

// ------------------------------- GEMM (tcgen05 TS) ---------------------------
// 3 row-tiles (384 nodes) per CTA -> grid 261 (2 waves @ 88% eff, same as R14,
// but 1.5x more per-CTA amortization). TMEM 512 cols: D ping-pong 0-127/128-255,
// A staging 256-511 (xH|xL|mH|mL, reused per tile). One commit per mbarrier.
#define SM_BIAS   64
#define SM_W      1024                       // 4 x 32KB: WrH|WrL|WlH|WlL
#define SM_TOTAL  (SM_W + 4 * 32768 + 128)   // ~132.2 KB

#define TMEM_COLS 512
#define TM_AXH 256
#define TM_AXL 320
#define TM_AMH 384
#define TM_AML 448

#define MMA_IDESC 0x8200490u

#if HAS_TCGEN05
// Stage a 128x128 fp32 tile -> TMEM bf16x2 hi/lo at given columns.
static __device__ __forceinline__ void stage_A(const float* __restrict__ src,
                                               int row0, int n, uint32_t tmem,
                                               int col_hi, int col_lo, int tid) {
    int row  = tid & 127;
    int half = tid >> 7;
    int gr   = row0 + row;
    uint32_t hi[32], lo[32];
    if (gr < n) {
        const float4* sr = (const float4*)(src + (size_t)gr * DD) + half * 16;
#pragma unroll
        for (int q = 0; q < 16; q++) {
            float4 v = sr[q];
            split_pack(v.x, v.y, hi[2 * q],     lo[2 * q]);
            split_pack(v.z, v.w, hi[2 * q + 1], lo[2 * q + 1]);
        }
    } else {
#pragma unroll
        for (int q = 0; q < 32; q++) { hi[q] = 0u; lo[q] = 0u; }
    }
    uint32_t base = tmem + (((uint32_t)(row >> 5)) << 21) + half * 32;
    TCGEN05_ST_32X32B_X32(base + col_hi, hi);
    TCGEN05_ST_32X32B_X32(base + col_lo, lo);
}

// 6 combos x 8 k-steps into D at d_off (fresh accumulate: first MMA acc=0).
static __device__ __forceinline__ void mma_batch(uint32_t tmem, uint32_t d_off,
                                                 uint32_t sb) {
    uint64_t dRh = MAKE_SMEM_DESC(sb + SM_W);
    uint64_t dRl = MAKE_SMEM_DESC(sb + SM_W + 32768);
    uint64_t dLh = MAKE_SMEM_DESC(sb + SM_W + 2 * 32768);
    uint64_t dLl = MAKE_SMEM_DESC(sb + SM_W + 3 * 32768);
    uint32_t ac[6] = {TM_AXH, TM_AXH, TM_AXL, TM_AMH, TM_AMH, TM_AML};
    uint64_t wd[6] = {dRh, dRl, dRh, dLh, dLl, dLh};
    bool acc = false;
#pragma unroll 1
    for (int c = 0; c < 6; c++) {
#pragma unroll
        for (int k = 0; k < 8; k++) {
            uint64_t off = (uint64_t)((k >> 2) * 1024 + (k & 3) * 2);
            TCGEN05_MMA_F16(tmem + d_off, tmem + ac[c] + k * 8, wd[c] + off,
                            MMA_IDESC, acc);
            acc = true;
        }
    }
}

// Epilogue for one tile: warp w reads rows (w%4)*32+lane, cols (w/4)*64..+63.
static __device__ __forceinline__ void epilogue(uint32_t tmem, uint32_t d_off,
                                                const float* bs, float* outp,
                                                int row0, int n, int relu,
                                                int wid, int lid) {
    int r = row0 + (wid & 3) * 32 + lid;
    int cbase = (wid >> 2) * 64;
#pragma unroll
    for (int cc = 0; cc < 2; cc++) {
        int cb = cbase + cc * 32;
        uint32_t regs[32];
        TCGEN05_LD_32X32B_X32(regs, tmem + d_off + cb);
        TCGEN05_WAIT_LD();
        if (r < n) {
            float4* orow = (float4*)(outp + (size_t)r * DD + cb);
#pragma unroll
            for (int q = 0; q < 8; q++) {
                float4 o;
                o.x = __uint_as_float(regs[4 * q + 0]) + bs[cb + 4 * q + 0];
                o.y = __uint_as_float(regs[4 * q + 1]) + bs[cb + 4 * q + 1];
                o.z = __uint_as_float(regs[4 * q + 2]) + bs[cb + 4 * q + 2];
                o.w = __uint_as_float(regs[4 * q + 3]) + bs[cb + 4 * q + 3];
                if (relu) {
                    o.x = fmaxf(o.x, 0.f); o.y = fmaxf(o.y, 0.f);
                    o.z = fmaxf(o.z, 0.f); o.w = fmaxf(o.w, 0.f);
                }
                orow[q] = o;
            }
        }
    }
}

// Stage tile + issue MMA into D buffer + commit mbar (warp0-elected).
static __device__ __forceinline__ void tile_mma(const float* feat, const float* meanf,
                                                int row0, int n, uint32_t tmem,
                                                uint32_t d_off, uint32_t sb,
                                                uint32_t mbar, int tid, int wid) {
    stage_A(feat,  row0, n, tmem, TM_AXH, TM_AXL, tid);
    stage_A(meanf, row0, n, tmem, TM_AMH, TM_AML, tid);
    TCGEN05_WAIT_ST();
    FENCE_PA();
    TCGEN05_FENCE_BEFORE();
    __syncthreads();
    if (wid == 0) {
        TCGEN05_FENCE_AFTER();
        if (elect_one_pred()) {
            mma_batch(tmem, d_off, sb);
            TCGEN05_COMMIT(mbar);
        }
    }
}
#endif

extern "C" __global__ void __launch_bounds__(256, 1)
k_gemm(const float* __restrict__ feat, const float* __restrict__ meanf,
       const uint4* __restrict__ wpre,
       const float* __restrict__ Wl, const float* __restrict__ Wr,
       const float* __restrict__ bias, float* __restrict__ outp, int n, int relu) {
    extern __shared__ char smem[];
    uint32_t sb = smem_u32(smem);
    int tid = threadIdx.x, wid = tid >> 5, lid = tid & 31;
    int row0 = blockIdx.x * 384;          // 3 tiles: row0 + t*128

#if HAS_TCGEN05
    if (wid == 0) { TCGEN05_ALLOC(sb, TMEM_COLS); } else { TCGEN05_RELQ(); }
    if (tid == 0) {
        MBARRIER_INIT(sb + 8,  1); MBARRIER_INIT(sb + 16, 1);
        MBARRIER_INIT(sb + 24, 1);
    }
    if (tid < 128) ((float*)(smem + SM_BIAS))[tid] = bias[tid];
    __syncthreads();
    uint32_t tmem;
    asm volatile("ld.shared.b32 %0, [%1];" : "=r"(tmem) : "r"(sb));

    // W image raw copy (128KB) — once per CTA, serves all 3 tiles
    {
        uint4* dst = (uint4*)(smem + SM_W);
#pragma unroll 8
        for (int i = tid; i < 8192; i += 256) dst[i] = wpre[i];
    }
    const float* bs = (const float*)(smem + SM_BIAS);

    // tile 0 -> D0, b0
    tile_mma(feat, meanf, row0, n, tmem, 0, sb, sb + 8, tid, wid);
    MBARRIER_WAIT_PARITY(sb + 8, 0);      // A cols free, D0 valid
    TCGEN05_FENCE_AFTER();

    // tile 1 -> D1, b1; epilogue D0 overlaps MMA1
    tile_mma(feat, meanf, row0 + 128, n, tmem, 128, sb, sb + 16, tid, wid);
    epilogue(tmem, 0, bs, outp, row0, n, relu, wid, lid);
    MBARRIER_WAIT_PARITY(sb + 16, 0);
    TCGEN05_FENCE_AFTER();
    __syncthreads();                      // all epilogue-D0 reads done

    // tile 2 -> D0, b2; epilogue D1 overlaps MMA2
    tile_mma(feat, meanf, row0 + 256, n, tmem, 0, sb, sb + 24, tid, wid);
    epilogue(tmem, 128, bs, outp, row0 + 128, n, relu, wid, lid);
    MBARRIER_WAIT_PARITY(sb + 24, 0);
    TCGEN05_FENCE_AFTER();
    epilogue(tmem, 0, bs, outp, row0 + 256, n, relu, wid, lid);

    TCGEN05_FENCE_BEFORE();
    __syncthreads();
    if (tid == 0) {
        MBARRIER_INVAL(sb + 8);  MBARRIER_INVAL(sb + 16);
        MBARRIER_INVAL(sb + 24);
    }
    __syncthreads();
    if (wid == 0) TCGEN05_DEALLOC(tmem, TMEM_COLS);
#else
    // Scalar fallback for the non-arch-specific compile pass (never runs on GB300).
    float* Wl_s = (float*)(smem);
    float* Wr_s = (float*)(smem + 65536);
    for (int i = tid; i < 128 * 128; i += 256) {
        Wl_s[i] = Wl[i];
        Wr_s[i] = Wr[i];
    }
    __syncthreads();
    for (int t = 0; t < 3; t++) {
        if (tid < 128) {
            int r = row0 + t * 128 + tid;
            if (r < n) {
                for (int c = 0; c < DD; c++) {
                    float acc = bias[c];
                    const float* wl = Wl_s + c * DD;
                    const float* wr = Wr_s + c * DD;
                    const float* xr = feat  + (size_t)r * DD;
                    const float* mr = meanf + (size_t)r * DD;
                    for (int k = 0; k < DD; k++)
                        acc += xr[k] * wr[k] + mr[k] * wl[k];
                    if (relu) acc = fmaxf(acc, 0.f);
                    outp[(size_t)r * DD + c] = acc;
                }
            }
        }
    }
#endif
}

// ------------------------------- launcher -----------------------------------
extern "C" void kernel_launch(void* const* d_in, const int* in_sizes, int n_in,
                              void* d_out, int out_size) {
    const float* x   = (const float*)d_in[0];
    const int*   ei  = (const int*)d_in[1];     // int32! (JAX x64 disabled)
    const float* W1l = (const float*)d_in[2];
    const float* W1r = (const float*)d_in[3];
    const float* b1  = (const float*)d_in[4];
    const float* W2l = (const float*)d_in[5];
    const float* W2r = (const float*)d_in[6];
    const float* b2  = (const float*)d_in[7];
    float*       out = (float*)d_out;

    cudaFuncSetAttribute(k_gemm, cudaFuncAttributeMaxDynamicSharedMemorySize, SM_TOTAL);

    void* pmean = nullptr;
    void* ph = nullptr;
    void* pw = nullptr;
    cudaGetSymbolAddress(&pmean, g_mean);
    cudaGetSymbolAddress(&ph, g_h);
    cudaGetSymbolAddress(&pw, g_wpre);
    float* mean = (float*)pmean;
    float* h    = (float*)ph;
    const uint4* w0 = (const uint4*)pw;
    const uint4* w1 = (const uint4*)((const unsigned char*)pw + 4 * 32768);

    // CSR build (shared by both layers) + W pre-conversion
    k_zero   <<<(NN + 255) / 256, 256>>>();
    k_hist   <<<(NE + 255) / 256, 256>>>(ei);
    k_wprep  <<<2, 256>>>(W1l, W1r, W2l, W2r);
    k_scanA  <<<196, 256>>>();
    k_scanB  <<<1,   256>>>();
    k_scanC  <<<196, 256>>>();
    k_scatter<<<(NE + 255) / 256, 256>>>(ei);

    int gemm_blocks = (NN + 383) / 384;   // 261 -> 2 waves @ 88% efficiency

    // layer 1
    k_agg<<<NN / 8, 256>>>(x, mean);      // 12500 blocks, warp/node
    k_gemm<<<gemm_blocks, 256, SM_TOTAL>>>(x, mean, w0, W1l, W1r, b1, h, NN, 1);

    // layer 2
    k_agg<<<NN / 8, 256>>>(h, mean);
    k_gemm<<<gemm_blocks, 256, SM_TOTAL>>>(h, mean, w1, W2l, W2r, b2, out, NN, 0);
}

// round 17
// speedup vs baseline: 1.1784x; 1.0194x over previous
#include <cuda_runtime.h>
#include <cuda_bf16.h>
#include <cstdint>

#define NN 100000
#define NE 640000
#define DD 128

#if defined(__CUDA_ARCH_FEAT_SM103_ALL) || defined(__CUDA_ARCH_FEAT_SM100_ALL) || \
    defined(__CUDA_ARCH_SPECIFIC__) || defined(__CUDA_ARCH_FEAT_SM101_ALL)
#define HAS_TCGEN05 1
#else
#define HAS_TCGEN05 0
#endif

// ----------------------------- device scratch -------------------------------
__device__ int   g_deg[NN];
__device__ int   g_rowstart[NN + 1];
__device__ int   g_cursor[NN];
__device__ int   g_bsum[256];
__device__ int   g_csr[NE];
__device__ float g_mean[(size_t)NN * DD];
__device__ float g_h[(size_t)NN * DD];
// Pre-converted W images: [layer][WrH|WrL|WlH|WlL], each seg 32KB, SW128 blocked
__device__ unsigned char g_wpre[2][4 * 32768];

// ----------------------------- PTX helpers ----------------------------------
static __device__ __forceinline__ uint32_t smem_u32(const void* p) {
    uint32_t a;
    asm("{ .reg .u64 t; cvta.to.shared.u64 t, %1; cvt.u32.u64 %0, t; }"
        : "=r"(a) : "l"(p));
    return a;
}

#if HAS_TCGEN05
static __device__ __forceinline__ uint32_t elect_one_pred() {
    uint32_t pred;
    asm volatile(
        "{\n\t.reg .pred p;\n\t"
        "elect.sync _|p, 0xFFFFFFFF;\n\t"
        "selp.b32 %0, 1, 0, p;\n\t}"
        : "=r"(pred));
    return pred;
}

#define TCGEN05_ALLOC(smem_addr, nCols) \
    asm volatile("tcgen05.alloc.cta_group::1.sync.aligned.shared::cta.b32 [%0], %1;" \
                 :: "r"((uint32_t)(smem_addr)), "r"((uint32_t)(nCols)) : "memory")
#define TCGEN05_RELQ() \
    asm volatile("tcgen05.relinquish_alloc_permit.cta_group::1.sync.aligned;")
#define TCGEN05_DEALLOC(tmem_addr, nCols) \
    asm volatile("tcgen05.dealloc.cta_group::1.sync.aligned.b32 %0, %1;" \
                 :: "r"(tmem_addr), "r"((uint32_t)(nCols)))
#define TCGEN05_COMMIT(mbar) \
    asm volatile("tcgen05.commit.cta_group::1.mbarrier::arrive::one.shared::cluster.b64 [%0];" \
                 :: "r"((uint32_t)(mbar)) : "memory")
#define TCGEN05_WAIT_LD()  asm volatile("tcgen05.wait::ld.sync.aligned;" ::: "memory")
#define TCGEN05_WAIT_ST()  asm volatile("tcgen05.wait::st.sync.aligned;" ::: "memory")
#define TCGEN05_FENCE_AFTER()  asm volatile("tcgen05.fence::after_thread_sync;" ::: "memory")
#define TCGEN05_FENCE_BEFORE() asm volatile("tcgen05.fence::before_thread_sync;" ::: "memory")
#define FENCE_PA() asm volatile("fence.proxy.async.shared::cta;" ::: "memory")

#define MBARRIER_INIT(m, c) \
    asm volatile("mbarrier.init.shared.b64 [%0], %1;" :: "r"((uint32_t)(m)), "r"((uint32_t)(c)) : "memory")
#define MBARRIER_INVAL(m) \
    asm volatile("mbarrier.inval.shared.b64 [%0];" :: "r"((uint32_t)(m)) : "memory")

#define MBARRIER_WAIT_PARITY(mbar_smem_addr, phase_parity) do { \
    uint32_t _mbar = (uint32_t)(mbar_smem_addr); \
    uint32_t _parity = (uint32_t)(phase_parity); \
    uint32_t _done; \
    asm volatile( \
        "{\n\t.reg .pred p;\n\t" \
        "mbarrier.try_wait.parity.acquire.cta.shared::cta.b64 p, [%1], %2;\n\t" \
        "selp.b32 %0, 1, 0, p;\n\t}" \
        : "=r"(_done) : "r"(_mbar), "r"(_parity) : "memory"); \
    if (!_done) { \
        asm volatile( \
            "{\n\t.reg .pred P1;\n\t" \
            "WAIT_LOOP_%=:\n\t" \
            "mbarrier.try_wait.parity.acquire.cta.shared::cta.b64 P1, [%0], %1, 0x989680;\n\t" \
            "@P1 bra.uni WAIT_DONE_%=;\n\t" \
            "bra.uni WAIT_LOOP_%=;\n\t" \
            "WAIT_DONE_%=:\n\t}" \
            :: "r"(_mbar), "r"(_parity) : "memory"); \
    } \
} while (0)

#define TCGEN05_LD_32X32B_X32(r, tmem_addr) \
    asm volatile( \
        "tcgen05.ld.sync.aligned.32x32b.x32.b32 " \
        "{%0, %1, %2, %3, %4, %5, %6, %7, " \
        " %8, %9, %10, %11, %12, %13, %14, %15, " \
        " %16, %17, %18, %19, %20, %21, %22, %23, " \
        " %24, %25, %26, %27, %28, %29, %30, %31}, [%32];" \
        : "=r"((r)[0]),  "=r"((r)[1]),  "=r"((r)[2]),  "=r"((r)[3]), \
          "=r"((r)[4]),  "=r"((r)[5]),  "=r"((r)[6]),  "=r"((r)[7]), \
          "=r"((r)[8]),  "=r"((r)[9]),  "=r"((r)[10]), "=r"((r)[11]), \
          "=r"((r)[12]), "=r"((r)[13]), "=r"((r)[14]), "=r"((r)[15]), \
          "=r"((r)[16]), "=r"((r)[17]), "=r"((r)[18]), "=r"((r)[19]), \
          "=r"((r)[20]), "=r"((r)[21]), "=r"((r)[22]), "=r"((r)[23]), \
          "=r"((r)[24]), "=r"((r)[25]), "=r"((r)[26]), "=r"((r)[27]), \
          "=r"((r)[28]), "=r"((r)[29]), "=r"((r)[30]), "=r"((r)[31]) \
        : "r"(tmem_addr))

#define TCGEN05_ST_32X32B_X32(tmem_addr, r) \
    asm volatile( \
        "tcgen05.st.sync.aligned.32x32b.x32.b32 [%0], " \
        "{%1, %2, %3, %4, %5, %6, %7, %8, " \
        " %9, %10, %11, %12, %13, %14, %15, %16, " \
        " %17, %18, %19, %20, %21, %22, %23, %24, " \
        " %25, %26, %27, %28, %29, %30, %31, %32};" \
        :: "r"(tmem_addr), \
           "r"((r)[0]),  "r"((r)[1]),  "r"((r)[2]),  "r"((r)[3]), \
           "r"((r)[4]),  "r"((r)[5]),  "r"((r)[6]),  "r"((r)[7]), \
           "r"((r)[8]),  "r"((r)[9]),  "r"((r)[10]), "r"((r)[11]), \
           "r"((r)[12]), "r"((r)[13]), "r"((r)[14]), "r"((r)[15]), \
           "r"((r)[16]), "r"((r)[17]), "r"((r)[18]), "r"((r)[19]), \
           "r"((r)[20]), "r"((r)[21]), "r"((r)[22]), "r"((r)[23]), \
           "r"((r)[24]), "r"((r)[25]), "r"((r)[26]), "r"((r)[27]), \
           "r"((r)[28]), "r"((r)[29]), "r"((r)[30]), "r"((r)[31]) \
        : "memory")

// TS-mode f16 MMA (A in TMEM, B via SMEM descriptor) — verbatim ptx_helpers.
#define TCGEN05_MMA_F16(d_tmem, a_tmem, b_smem_desc, idesc, enable_d) do { \
    uint32_t _enable = (enable_d) ? 1 : 0; \
    uint32_t _zero = 0; \
    asm volatile( \
        "{\n\t" \
        ".reg .pred p;\n\t" \
        "setp.ne.u32 p, %6, 0;\n\t" \
        "tcgen05.mma.cta_group::1.kind::f16 [%0], [%1], %2, %3, " \
        "{%4, %4, %4, %4}, p;\n\t" \
        "}" \
        :: "r"(d_tmem), "r"(a_tmem), "l"(b_smem_desc), "r"(idesc), \
           "r"(_zero), "r"(_zero), "r"(_enable) \
        : "memory"); \
} while(0)

static constexpr uint64_t SMEM_DESC_BASE_SW128 =
    (uint64_t(2) << 61) | (uint64_t(1) << 46) | (uint64_t(64) << 32) | (uint64_t(1) << 16);
#define MAKE_SMEM_DESC(base_addr) \
    (SMEM_DESC_BASE_SW128 | ((uint64_t)((base_addr) >> 4) & 0x3FFF))
#endif  // HAS_TCGEN05

// ------------------------------ CSR build -----------------------------------
__global__ void k_hist(const int* __restrict__ ei) {
    int e = blockIdx.x * 256 + threadIdx.x;
    if (e < NE) {
        int d = ei[NE + e];
        atomicAdd(&g_deg[d], 1);
    }
}

__global__ void k_scanA() {
    __shared__ int sh[256];
    int b = blockIdx.x, t = threadIdx.x;
    int base = b * 512 + t * 2;
    int d0 = (base     < NN) ? g_deg[base]     : 0;
    int d1 = (base + 1 < NN) ? g_deg[base + 1] : 0;
    int s = d0 + d1;
    sh[t] = s; __syncthreads();
    for (int off = 1; off < 256; off <<= 1) {
        int v = (t >= off) ? sh[t - off] : 0;
        __syncthreads();
        sh[t] += v;
        __syncthreads();
    }
    int excl = sh[t] - s;
    if (base     < NN) g_rowstart[base]     = excl;
    if (base + 1 < NN) g_rowstart[base + 1] = excl + d0;
    if (t == 255) g_bsum[b] = sh[255];
}

__global__ void k_scanB() {
    __shared__ int sh[256];
    int t = threadIdx.x;
    int v = (t < 196) ? g_bsum[t] : 0;
    sh[t] = v; __syncthreads();
    for (int off = 1; off < 256; off <<= 1) {
        int u = (t >= off) ? sh[t - off] : 0;
        __syncthreads();
        sh[t] += u;
        __syncthreads();
    }
    if (t < 196) g_bsum[t] = sh[t] - v;   // exclusive
    if (t == 255) g_rowstart[NN] = sh[255];
}

__global__ void k_scanC() {
    int b = blockIdx.x, t = threadIdx.x;
    int off = g_bsum[b];
    int base = b * 512 + t * 2;
#pragma unroll
    for (int j = 0; j < 2; j++) {
        int i = base + j;
        if (i < NN) {
            int v = g_rowstart[i] + off;
            g_rowstart[i] = v;
            g_cursor[i]   = v;
        }
    }
}

__global__ void k_scatter(const int* __restrict__ ei) {
    int e = blockIdx.x * 256 + threadIdx.x;
    if (e < NE) {
        int s = ei[e];
        int d = ei[NE + e];
        int p = atomicAdd(&g_cursor[d], 1);
        g_csr[p] = s;
    }
}

// ------------------------------ aggregation ---------------------------------
// One warp per destination node, unrolled x4 (MLP>=4 hides L2/TLB latency).
__global__ void k_agg(const float* __restrict__ feat, float* __restrict__ om) {
    int w = (blockIdx.x * blockDim.x + threadIdx.x) >> 5;
    int lane = threadIdx.x & 31;
    if (w >= NN) return;
    int beg = g_rowstart[w], end = g_rowstart[w + 1];
    float4 a = make_float4(0.f, 0.f, 0.f, 0.f);
    int i = beg;
#pragma unroll 1
    for (; i + 4 <= end; i += 4) {
        int s0 = g_csr[i];
        int s1 = g_csr[i + 1];
        int s2 = g_csr[i + 2];
        int s3 = g_csr[i + 3];
        float4 v0 = ((const float4*)(feat + (size_t)s0 * DD))[lane];
        float4 v1 = ((const float4*)(feat + (size_t)s1 * DD))[lane];
        float4 v2 = ((const float4*)(feat + (size_t)s2 * DD))[lane];
        float4 v3 = ((const float4*)(feat + (size_t)s3 * DD))[lane];
        a.x += (v0.x + v1.x) + (v2.x + v3.x);
        a.y += (v0.y + v1.y) + (v2.y + v3.y);
        a.z += (v0.z + v1.z) + (v2.z + v3.z);
        a.w += (v0.w + v1.w) + (v2.w + v3.w);
    }
#pragma unroll 1
    for (; i < end; i++) {
        int s = g_csr[i];
        float4 v = ((const float4*)(feat + (size_t)s * DD))[lane];
        a.x += v.x; a.y += v.y; a.z += v.z; a.w += v.w;
    }
    float inv = 1.0f / (float)max(end - beg, 1);
    a.x *= inv; a.y *= inv; a.z *= inv; a.w *= inv;
    ((float4*)(om + (size_t)w * DD))[lane] = a;
}

// --------------------------- W pre-conversion --------------------------------
static __device__ __forceinline__ void split_pack(float a, float b,
                                                  uint32_t& hi, uint32_t& lo) {
    __nv_bfloat16 ah = __float2bfloat16(a);
    __nv_bfloat16 bh = __float2bfloat16(b);
    __nv_bfloat16 al = __float2bfloat16(a - __bfloat162float(ah));
    __nv_bfloat16 bl = __float2bfloat16(b - __bfloat162float(bh));
    __nv_bfloat162 H = __halves2bfloat162(ah, bh);
    __nv_bfloat162 L = __halves2bfloat162(al, bl);
    hi = *reinterpret_cast<uint32_t*>(&H);
    lo = *reinterpret_cast<uint32_t*>(&L);
}

static __device__ __forceinline__ void wconv(const float* __restrict__ src,
                                             unsigned char* __restrict__ hi_seg,
                                             unsigned char* __restrict__ lo_seg,
                                             int tid) {
#pragma unroll 4
    for (int i = 0; i < 16; i++) {
        int idx = tid + 256 * i;
        int r   = idx >> 5;
        int c4  = idx & 31;
        float4 v = *(const float4*)(src + (size_t)r * DD + c4 * 4);
        uint32_t h01, l01, h23, l23;
        split_pack(v.x, v.y, h01, l01);
        split_pack(v.z, v.w, h23, l23);
        uint32_t off = ((uint32_t)(c4 >> 4) * 16u + (uint32_t)(r >> 3)) * 1024u
                     + (uint32_t)(r & 7) * 128u + (uint32_t)(c4 & 15) * 8u;
        uint32_t sw = off ^ ((off >> 3) & 0x70);
        *(uint64_t*)(hi_seg + sw) = ((uint64_t)h01) | ((uint64_t)h23 << 32);
        *(uint64_t*)(lo_seg + sw) = ((uint64_t)l01) | ((uint64_t)l23 << 32);
    }
}

__global__ void k_wprep(const float* __restrict__ W1l, const float* __restrict__ W1r,
                        const float* __restrict__ W2l, const float* __restrict__ W2r) {
    int l = blockIdx.x;
    const float* Wr = l ? W2r : W1r;
    const float* Wl = l ? W2l : W1l;
    unsigned char* base = g_wpre[l];
    wconv(Wr, base,             base + 32768,     threadIdx.x);
    wconv(Wl, base + 2 * 32768, base + 3 * 32768, threadIdx.x);
}

// ------------------------------- GEMM (tcgen05 TS) ---------------------------
// 3 row-tiles (384 nodes) per CTA -> grid 261 (2 waves @ 88% eff).
// TMEM 512 cols: D ping-pong 0-127/128-255, A staging 256-511.
#define SM_BIAS   64
#define SM_W      1024                       // 4 x 32KB: WrH|WrL|WlH|WlL
#define SM_TOTAL  (SM_W + 4 * 32768 + 128)   // ~132.2 KB

#define TMEM_COLS 512
#define TM_AXH 256
#define TM_AXL 320
#define TM_AMH 384
#define TM_AML 448

#define MMA_IDESC 0x8200490u

#if HAS_TCGEN05
// Stage a 128x128 fp32 tile -> TMEM bf16x2 hi/lo at given columns.
static __device__ __forceinline__ void stage_A(const float* __restrict__ src,
                                               int row0, int n, uint32_t tmem,
                                               int col_hi, int col_lo, int tid) {
    int row  = tid & 127;
    int half = tid >> 7;
    int gr   = row0 + row;
    uint32_t hi[32], lo[32];
    if (gr < n) {
        const float4* sr = (const float4*)(src + (size_t)gr * DD) + half * 16;
#pragma unroll
        for (int q = 0; q < 16; q++) {
            float4 v = sr[q];
            split_pack(v.x, v.y, hi[2 * q],     lo[2 * q]);
            split_pack(v.z, v.w, hi[2 * q + 1], lo[2 * q + 1]);
        }
    } else {
#pragma unroll
        for (int q = 0; q < 32; q++) { hi[q] = 0u; lo[q] = 0u; }
    }
    uint32_t base = tmem + (((uint32_t)(row >> 5)) << 21) + half * 32;
    TCGEN05_ST_32X32B_X32(base + col_hi, hi);
    TCGEN05_ST_32X32B_X32(base + col_lo, lo);
}

// 6 combos x 8 k-steps into D at d_off (fresh accumulate: first MMA acc=0).
static __device__ __forceinline__ void mma_batch(uint32_t tmem, uint32_t d_off,
                                                 uint32_t sb) {
    uint64_t dRh = MAKE_SMEM_DESC(sb + SM_W);
    uint64_t dRl = MAKE_SMEM_DESC(sb + SM_W + 32768);
    uint64_t dLh = MAKE_SMEM_DESC(sb + SM_W + 2 * 32768);
    uint64_t dLl = MAKE_SMEM_DESC(sb + SM_W + 3 * 32768);
    uint32_t ac[6] = {TM_AXH, TM_AXH, TM_AXL, TM_AMH, TM_AMH, TM_AML};
    uint64_t wd[6] = {dRh, dRl, dRh, dLh, dLl, dLh};
    bool acc = false;
#pragma unroll 1
    for (int c = 0; c < 6; c++) {
#pragma unroll
        for (int k = 0; k < 8; k++) {
            uint64_t off = (uint64_t)((k >> 2) * 1024 + (k & 3) * 2);
            TCGEN05_MMA_F16(tmem + d_off, tmem + ac[c] + k * 8, wd[c] + off,
                            MMA_IDESC, acc);
            acc = true;
        }
    }
}

// Epilogue for one tile: warp w reads rows (w%4)*32+lane, cols (w/4)*64..+63.
static __device__ __forceinline__ void epilogue(uint32_t tmem, uint32_t d_off,
                                                const float* bs, float* outp,
                                                int row0, int n, int relu,
                                                int wid, int lid) {
    int r = row0 + (wid & 3) * 32 + lid;
    int cbase = (wid >> 2) * 64;
#pragma unroll
    for (int cc = 0; cc < 2; cc++) {
        int cb = cbase + cc * 32;
        uint32_t regs[32];
        TCGEN05_LD_32X32B_X32(regs, tmem + d_off + cb);
        TCGEN05_WAIT_LD();
        if (r < n) {
            float4* orow = (float4*)(outp + (size_t)r * DD + cb);
#pragma unroll
            for (int q = 0; q < 8; q++) {
                float4 o;
                o.x = __uint_as_float(regs[4 * q + 0]) + bs[cb + 4 * q + 0];
                o.y = __uint_as_float(regs[4 * q + 1]) + bs[cb + 4 * q + 1];
                o.z = __uint_as_float(regs[4 * q + 2]) + bs[cb + 4 * q + 2];
                o.w = __uint_as_float(regs[4 * q + 3]) + bs[cb + 4 * q + 3];
                if (relu) {
                    o.x = fmaxf(o.x, 0.f); o.y = fmaxf(o.y, 0.f);
                    o.z = fmaxf(o.z, 0.f); o.w = fmaxf(o.w, 0.f);
                }
                orow[q] = o;
            }
        }
    }
}

// Stage tile + issue MMA into D buffer + commit mbar (warp0-elected).
static __device__ __forceinline__ void tile_mma(const float* feat, const float* meanf,
                                                int row0, int n, uint32_t tmem,
                                                uint32_t d_off, uint32_t sb,
                                                uint32_t mbar, int tid, int wid) {
    stage_A(feat,  row0, n, tmem, TM_AXH, TM_AXL, tid);
    stage_A(meanf, row0, n, tmem, TM_AMH, TM_AML, tid);
    TCGEN05_WAIT_ST();
    FENCE_PA();
    TCGEN05_FENCE_BEFORE();
    __syncthreads();
    if (wid == 0) {
        TCGEN05_FENCE_AFTER();
        if (elect_one_pred()) {
            mma_batch(tmem, d_off, sb);
            TCGEN05_COMMIT(mbar);
        }
    }
}
#endif

extern "C" __global__ void __launch_bounds__(256, 1)
k_gemm(const float* __restrict__ feat, const float* __restrict__ meanf,
       const uint4* __restrict__ wpre,
       const float* __restrict__ Wl, const float* __restrict__ Wr,
       const float* __restrict__ bias, float* __restrict__ outp, int n, int relu) {
    extern __shared__ char smem[];
    uint32_t sb = smem_u32(smem);
    int tid = threadIdx.x, wid = tid >> 5, lid = tid & 31;
    int row0 = blockIdx.x * 384;          // 3 tiles: row0 + t*128

#if HAS_TCGEN05
    if (wid == 0) { TCGEN05_ALLOC(sb, TMEM_COLS); } else { TCGEN05_RELQ(); }
    if (tid == 0) {
        MBARRIER_INIT(sb + 8,  1); MBARRIER_INIT(sb + 16, 1);
        MBARRIER_INIT(sb + 24, 1);
    }
    if (tid < 128) ((float*)(smem + SM_BIAS))[tid] = bias[tid];
    __syncthreads();
    uint32_t tmem;
    asm volatile("ld.shared.b32 %0, [%1];" : "=r"(tmem) : "r"(sb));

    // W image raw copy (128KB) — once per CTA, serves all 3 tiles
    {
        uint4* dst = (uint4*)(smem + SM_W);
#pragma unroll 8
        for (int i = tid; i < 8192; i += 256) dst[i] = wpre[i];
    }
    const float* bs = (const float*)(smem + SM_BIAS);

    // tile 0 -> D0, b0
    tile_mma(feat, meanf, row0, n, tmem, 0, sb, sb + 8, tid, wid);
    MBARRIER_WAIT_PARITY(sb + 8, 0);      // A cols free, D0 valid
    TCGEN05_FENCE_AFTER();

    // tile 1 -> D1, b1; epilogue D0 overlaps MMA1
    tile_mma(feat, meanf, row0 + 128, n, tmem, 128, sb, sb + 16, tid, wid);
    epilogue(tmem, 0, bs, outp, row0, n, relu, wid, lid);
    MBARRIER_WAIT_PARITY(sb + 16, 0);
    TCGEN05_FENCE_AFTER();
    __syncthreads();                      // all epilogue-D0 reads done

    // tile 2 -> D0, b2; epilogue D1 overlaps MMA2
    tile_mma(feat, meanf, row0 + 256, n, tmem, 0, sb, sb + 24, tid, wid);
    epilogue(tmem, 128, bs, outp, row0 + 128, n, relu, wid, lid);
    MBARRIER_WAIT_PARITY(sb + 24, 0);
    TCGEN05_FENCE_AFTER();
    epilogue(tmem, 0, bs, outp, row0 + 256, n, relu, wid, lid);

    TCGEN05_FENCE_BEFORE();
    __syncthreads();
    if (tid == 0) {
        MBARRIER_INVAL(sb + 8);  MBARRIER_INVAL(sb + 16);
        MBARRIER_INVAL(sb + 24);
    }
    __syncthreads();
    if (wid == 0) TCGEN05_DEALLOC(tmem, TMEM_COLS);
#else
    // Scalar fallback for the non-arch-specific compile pass (never runs on GB300).
    float* Wl_s = (float*)(smem);
    float* Wr_s = (float*)(smem + 65536);
    for (int i = tid; i < 128 * 128; i += 256) {
        Wl_s[i] = Wl[i];
        Wr_s[i] = Wr[i];
    }
    __syncthreads();
    for (int t = 0; t < 3; t++) {
        if (tid < 128) {
            int r = row0 + t * 128 + tid;
            if (r < n) {
                for (int c = 0; c < DD; c++) {
                    float acc = bias[c];
                    const float* wl = Wl_s + c * DD;
                    const float* wr = Wr_s + c * DD;
                    const float* xr = feat  + (size_t)r * DD;
                    const float* mr = meanf + (size_t)r * DD;
                    for (int k = 0; k < DD; k++)
                        acc += xr[k] * wr[k] + mr[k] * wl[k];
                    if (relu) acc = fmaxf(acc, 0.f);
                    outp[(size_t)r * DD + c] = acc;
                }
            }
        }
    }
#endif
}

// ------------------------------- launcher -----------------------------------
extern "C" void kernel_launch(void* const* d_in, const int* in_sizes, int n_in,
                              void* d_out, int out_size) {
    const float* x   = (const float*)d_in[0];
    const int*   ei  = (const int*)d_in[1];     // int32! (JAX x64 disabled)
    const float* W1l = (const float*)d_in[2];
    const float* W1r = (const float*)d_in[3];
    const float* b1  = (const float*)d_in[4];
    const float* W2l = (const float*)d_in[5];
    const float* W2r = (const float*)d_in[6];
    const float* b2  = (const float*)d_in[7];
    float*       out = (float*)d_out;

    cudaFuncSetAttribute(k_gemm, cudaFuncAttributeMaxDynamicSharedMemorySize, SM_TOTAL);

    void* pmean = nullptr;
    void* ph = nullptr;
    void* pw = nullptr;
    void* pdeg = nullptr;
    cudaGetSymbolAddress(&pmean, g_mean);
    cudaGetSymbolAddress(&ph, g_h);
    cudaGetSymbolAddress(&pw, g_wpre);
    cudaGetSymbolAddress(&pdeg, g_deg);
    float* mean = (float*)pmean;
    float* h    = (float*)ph;
    const uint4* w0 = (const uint4*)pw;
    const uint4* w1 = (const uint4*)((const unsigned char*)pw + 4 * 32768);

    // CSR build (shared by both layers). Launch order keeps k_agg as the 6th
    // kernel launch so the fixed ncu window (-s 5 -c 1) profiles it.
    cudaMemsetAsync(pdeg, 0, NN * sizeof(int));
    k_hist   <<<(NE + 255) / 256, 256>>>(ei);
    k_scanA  <<<196, 256>>>();
    k_scanB  <<<1,   256>>>();
    k_scanC  <<<196, 256>>>();
    k_scatter<<<(NE + 255) / 256, 256>>>(ei);

    int gemm_blocks = (NN + 383) / 384;   // 261 -> 2 waves @ 88% efficiency

    // layer 1
    k_agg<<<NN / 8, 256>>>(x, mean);      // 12500 blocks, warp/node
    k_wprep<<<2, 256>>>(W1l, W1r, W2l, W2r);   // before first k_gemm use
    k_gemm<<<gemm_blocks, 256, SM_TOTAL>>>(x, mean, w0, W1l, W1r, b1, h, NN, 1);

    // layer 2
    k_agg<<<NN / 8, 256>>>(h, mean);
    k_gemm<<<gemm_blocks, 256, SM_TOTAL>>>(h, mean, w1, W2l, W2r, b2, out, NN, 0);
}